// round 15
// baseline (speedup 1.0000x reference)
#include <cuda_runtime.h>
#include <cuda_bf16.h>
#include <cstdint>

#define NUM_Q 3000
#define BATCH 32
#define SEQ 500
#define MTOT (BATCH * SEQ)
#define KX (2 * NUM_Q)

typedef __nv_bfloat16 bf16;
typedef __nv_bfloat162 bf162;

// ---------------- scratch (bf16 hi/lo planes) ----------------
__device__ __align__(256) bf16 g_xh[(size_t)MTOT * KX + 64];
__device__ __align__(256) bf16 g_xl[(size_t)MTOT * KX + 64];
__device__ __align__(256) bf16 g_qTh[512 * KX + 64];
__device__ __align__(256) bf16 g_qTl[512 * KX + 64];
__device__ __align__(256) bf16 g_wh[3465216];
__device__ __align__(256) bf16 g_wl[3465216];
__device__ __align__(256) bf16 g_xeh[(size_t)MTOT * 512];
__device__ __align__(256) bf16 g_xel[(size_t)MTOT * 512];
__device__ __align__(256) bf16 g_gh[2ll * MTOT * 256];
__device__ __align__(256) bf16 g_gl[2ll * MTOT * 256];
__device__ __align__(256) bf16 g_gTh[2ll * 32 * 256 * 512];
__device__ __align__(256) bf16 g_gTl[2ll * 32 * 256 * 512];
__device__ __align__(256) bf16 g_ah[(size_t)MTOT * 512];
__device__ __align__(256) bf16 g_al[(size_t)MTOT * 512];
__device__ __align__(256) bf16 g_ensh[(size_t)MTOT * 512];
__device__ __align__(256) bf16 g_ensl[(size_t)MTOT * 512];
__device__ float g_xproj[2ll * MTOT * 768];
__device__ float g_out[2ll * MTOT * 256];
__device__ float g_attn[(size_t)MTOT * 512];
__device__ float g_colsum[BATCH * 256];
__device__ float g_biasL[2 * NUM_Q];     // fccb | fctb
__device__ float g_biasP[2 * 768];       // g1bih | g2bih

#define WOFF_W1 0
#define WOFF_W2 196608
#define WOFF_WC 393216
#define WOFF_WT 1161216
#define WOFF_WE 1929216

// ---------------- helpers ----------------
__device__ __forceinline__ unsigned long long dupf2(float x) {
    unsigned long long r; asm("mov.b64 %0, {%1, %1};" : "=l"(r) : "f"(x)); return r;
}
__device__ __forceinline__ float2 unpackf2(unsigned long long v) {
    float2 f; asm("mov.b64 {%0, %1}, %2;" : "=f"(f.x), "=f"(f.y) : "l"(v)); return f;
}
#define FMA2(d, a, b) asm("fma.rn.f32x2 %0, %1, %2, %0;" : "+l"(d) : "l"(a), "l"(b))

__device__ __forceinline__ unsigned smem_u32(const void* p) {
    unsigned r;
    asm("{ .reg .u64 t; cvta.to.shared.u64 t, %1; cvt.u32.u64 %0, t; }" : "=r"(r) : "l"(p));
    return r;
}
#define CLUSTER_SYNC_() do { \
    asm volatile("barrier.cluster.arrive.aligned;" ::: "memory"); \
    asm volatile("barrier.cluster.wait.aligned;"   ::: "memory"); } while (0)

#define LDSM4(r, addr) asm volatile( \
    "ldmatrix.sync.aligned.m8n8.x4.shared.b16 {%0,%1,%2,%3}, [%4];" \
    : "=r"((r)[0]), "=r"((r)[1]), "=r"((r)[2]), "=r"((r)[3]) : "r"(addr))

#define MMA_BF16(c, a, b0, b1) asm volatile( \
    "mma.sync.aligned.m16n8k16.row.col.f32.bf16.bf16.f32 " \
    "{%0,%1,%2,%3}, {%4,%5,%6,%7}, {%8,%9}, {%0,%1,%2,%3};" \
    : "+f"((c)[0]), "+f"((c)[1]), "+f"((c)[2]), "+f"((c)[3]) \
    : "r"((a)[0]), "r"((a)[1]), "r"((a)[2]), "r"((a)[3]), "r"(b0), "r"(b1))

__device__ __forceinline__ void cpa16(uint32_t dst, const void* src, unsigned bytes) {
    asm volatile("cp.async.cg.shared.global [%0], [%1], 16, %2;"
                 :: "r"(dst), "l"(src), "r"(bytes) : "memory");
}
#define CP_COMMIT() asm volatile("cp.async.commit_group;" ::: "memory")
#define CP_WAIT1()  asm volatile("cp.async.wait_group 1;" ::: "memory")

__device__ __forceinline__ void split2(float a, float b, bf162& h, bf162& l) {
    h = __floats2bfloat162_rn(a, b);
    float2 f = __bfloat1622float2(h);
    l = __floats2bfloat162_rn(a - f.x, b - f.y);
}

// ---------------- generic fp32 -> bf16 hi/lo split ----------------
__global__ void split4_kernel(const float4* __restrict__ s,
                              bf16* __restrict__ h, bf16* __restrict__ l, long n4) {
    long i = (long)blockIdx.x * 256 + threadIdx.x;
    if (i < n4) {
        float4 v = s[i];
        bf162 h01, l01, h23, l23;
        split2(v.x, v.y, h01, l01);
        split2(v.z, v.w, h23, l23);
        ((bf162*)h)[i * 2] = h01;     ((bf162*)h)[i * 2 + 1] = h23;
        ((bf162*)l)[i * 2] = l01;     ((bf162*)l)[i * 2 + 1] = l23;
    }
}

// ---------------- concat two bias vectors ----------------
__global__ void cat2_kernel(const float* __restrict__ a, const float* __restrict__ b,
                            float* __restrict__ d, int n) {
    int i = blockIdx.x * 256 + threadIdx.x;
    if (i < n) d[i] = a[i];
    else if (i < 2 * n) d[i] = b[i - n];
}

// ---------------- pack question tables transposed + split ----------------
__global__ void packqT_kernel(const float* __restrict__ qh, const float* __restrict__ qd,
                              bf16* __restrict__ th, bf16* __restrict__ tl) {
    __shared__ float t[32][33];
    int kb = blockIdx.x * 32, cb = blockIdx.y * 32;
    const float* src = (cb < 256) ? qh : qd;
    int cc0 = cb & 255;
    int x = threadIdx.x, y = threadIdx.y;
    for (int yy = y; yy < 32; yy += 8) {
        int k = kb + yy;
        t[yy][x] = (k < KX) ? src[(long)k * 256 + cc0 + x] : 0.f;
    }
    __syncthreads();
    if (kb + x < KX)
        for (int yy = y; yy < 32; yy += 8) {
            float v = t[x][yy];
            bf16 hv = __float2bfloat16(v);
            th[(long)(cb + yy) * KX + kb + x] = hv;
            tl[(long)(cb + yy) * KX + kb + x] = __float2bfloat16(v - __bfloat162float(hv));
        }
}

// ---------------- transpose + split GRU outputs ----------------
__global__ void transpSplit_kernel(const float* __restrict__ g,
                                   bf16* __restrict__ th, bf16* __restrict__ tl) {
    __shared__ float tile[32][33];
    int gb = blockIdx.z;
    int t0 = blockIdx.x * 32, j0 = blockIdx.y * 32;
    const float* src = g + (long)gb * SEQ * 256;
    int x = threadIdx.x, y = threadIdx.y;
    for (int yy = y; yy < 32; yy += 8) {
        int t = t0 + yy;
        tile[yy][x] = (t < SEQ) ? src[(long)t * 256 + j0 + x] : 0.f;
    }
    __syncthreads();
    for (int yy = y; yy < 32; yy += 8) {
        long o = (long)(gb * 256 + j0 + yy) * 512 + t0 + x;
        float v = tile[x][yy];
        bf16 hv = __float2bfloat16(v);
        th[o] = hv;
        tl[o] = __float2bfloat16(v - __bfloat162float(hv));
    }
}

// ---------------- pipelined bf16-split tensor-core NT GEMM ----------------
// C = (Ah+Al)@(Bh+Bl)^T dropping Al*Bl. 2-stage cp.async double buffer, 2 CTAs/SM.
// OUT=0: fp32 C (+bias, bias += z*sBias). OUT=1: split bf16 Ch/Cl.
#define PIPE 2
#define STG_B 40960
#define MMA_SMEM (PIPE * STG_B)

template <int OUT>
__global__ __launch_bounds__(256, 2)
void mma_gemm(const bf16* __restrict__ Ah, const bf16* __restrict__ Al,
              const bf16* __restrict__ Bh, const bf16* __restrict__ Bl,
              float* __restrict__ C, bf16* __restrict__ Ch, bf16* __restrict__ Cl,
              const float* __restrict__ bias, long sBias,
              int M, int N, int K, int lda, int ldb, int ldc,
              long sA, long sB, long sC) {
    extern __shared__ __align__(16) bf16 smp[];
    const int z = blockIdx.z;
    Ah += (long)z * sA; Al += (long)z * sA;
    Bh += (long)z * sB; Bl += (long)z * sB;
    if (bias) bias += (long)z * sBias;
    const long coff = (long)z * sC;
    const int row0 = blockIdx.y * 128, col0 = blockIdx.x * 128;
    const int tid = threadIdx.x, lane = tid & 31, wid = tid >> 5;
    const int wm0 = (wid & 3) * 32, wn0 = (wid >> 2) * 64;

    const int r = tid >> 1;
    const int c0 = (tid & 1) * 2;
    int arow = row0 + r; if (arow >= M) arow = M - 1;
    int brow = col0 + r; if (brow >= N) brow = N - 1;
    const char* pAh = (const char*)(Ah + (long)arow * lda);
    const char* pAl = (const char*)(Al + (long)arow * lda);
    const char* pBh = (const char*)(Bh + (long)brow * ldb);
    const char* pBl = (const char*)(Bl + (long)brow * ldb);
    const uint32_t dst0 = smem_u32(smp) + (uint32_t)(r * 80 + c0 * 16);
    const int NIT = (K + 31) >> 5;

    auto issue = [&](int it) {
        const uint32_t base = dst0 + (uint32_t)(it & 1) * STG_B;
        const int k0 = it << 5;
        #pragma unroll
        for (int cc = 0; cc < 2; ++cc) {
            int kh = k0 + (c0 + cc) * 8;
            int rem = K - kh;
            unsigned bytes = rem >= 8 ? 16u : (rem > 0 ? (unsigned)(rem * 2) : 0u);
            long go = (long)kh * 2;
            cpa16(base + cc * 16,         pAh + go, bytes);
            cpa16(base + 10240 + cc * 16, pAl + go, bytes);
            cpa16(base + 20480 + cc * 16, pBh + go, bytes);
            cpa16(base + 30720 + cc * 16, pBl + go, bytes);
        }
        CP_COMMIT();
    };

    float c[2][8][4];
    #pragma unroll
    for (int a = 0; a < 2; ++a)
        #pragma unroll
        for (int b = 0; b < 8; ++b)
            #pragma unroll
            for (int d = 0; d < 4; ++d) c[a][b][d] = 0.f;

    issue(0); issue(1);

    for (int it = 0; it < NIT; ++it) {
        CP_WAIT1();
        __syncthreads();

        const bf16* s0 = smp + (size_t)(it & 1) * (STG_B / 2);
        const bf16* s1 = s0 + 5120;
        const bf16* s2 = s0 + 10240;
        const bf16* s3 = s0 + 15360;

        #pragma unroll
        for (int kk = 0; kk < 2; ++kk) {
            uint32_t ah[2][4], al[2][4];
            #pragma unroll
            for (int mt = 0; mt < 2; ++mt) {
                int ra = wm0 + mt * 16 + (lane & 15);
                int ca = kk * 16 + ((lane >> 4) << 3);
                LDSM4(ah[mt], smem_u32(s0 + ra * 40 + ca));
                LDSM4(al[mt], smem_u32(s1 + ra * 40 + ca));
            }
            #pragma unroll
            for (int nt2 = 0; nt2 < 4; ++nt2) {
                int rb = wn0 + nt2 * 16 + (lane & 7) + ((lane >> 4) << 3);
                int cb2 = kk * 16 + (((lane >> 3) & 1) << 3);
                uint32_t bh[4], bl[4];
                LDSM4(bh, smem_u32(s2 + rb * 40 + cb2));
                LDSM4(bl, smem_u32(s3 + rb * 40 + cb2));
                #pragma unroll
                for (int mt = 0; mt < 2; ++mt)
                    #pragma unroll
                    for (int hh = 0; hh < 2; ++hh) {
                        float* cc = c[mt][nt2 * 2 + hh];
                        MMA_BF16(cc, ah[mt], bh[hh * 2], bh[hh * 2 + 1]);
                        MMA_BF16(cc, al[mt], bh[hh * 2], bh[hh * 2 + 1]);
                        MMA_BF16(cc, ah[mt], bl[hh * 2], bl[hh * 2 + 1]);
                    }
            }
        }
        __syncthreads();
        if (it + 2 < NIT) issue(it + 2);
        else CP_COMMIT();
    }

    const int g = lane >> 2, tg = lane & 3;
    #pragma unroll
    for (int mt = 0; mt < 2; ++mt)
        #pragma unroll
        for (int nt = 0; nt < 8; ++nt) {
            int m0 = row0 + wm0 + mt * 16 + g;
            int n0 = col0 + wn0 + nt * 8 + tg * 2;
            if (n0 >= N) continue;
            float v0 = c[mt][nt][0], v1 = c[mt][nt][1];
            float v2 = c[mt][nt][2], v3 = c[mt][nt][3];
            if (OUT == 0) {
                float b0 = bias ? bias[n0] : 0.f;
                float b1 = bias ? bias[n0 + 1] : 0.f;
                if (m0 < M)
                    *(float2*)&C[coff + (long)m0 * ldc + n0] = make_float2(v0 + b0, v1 + b1);
                if (m0 + 8 < M)
                    *(float2*)&C[coff + (long)(m0 + 8) * ldc + n0] = make_float2(v2 + b0, v3 + b1);
            } else {
                bf162 h01, l01, h23, l23;
                split2(v0, v1, h01, l01);
                split2(v2, v3, h23, l23);
                if (m0 < M) {
                    *(bf162*)&Ch[coff + (long)m0 * ldc + n0] = h01;
                    *(bf162*)&Cl[coff + (long)m0 * ldc + n0] = l01;
                }
                if (m0 + 8 < M) {
                    *(bf162*)&Ch[coff + (long)(m0 + 8) * ldc + n0] = h23;
                    *(bf162*)&Cl[coff + (long)(m0 + 8) * ldc + n0] = l23;
                }
            }
        }
}

// ---------------- fused attention-apply: grid.x 0-1 -> attn@out_d ; 2-3 -> colsum - attn@out_h ----------------
__global__ __launch_bounds__(256, 2)
void mma_apply(const bf16* __restrict__ Ah, const bf16* __restrict__ Al,
               const bf16* __restrict__ Bdh, const bf16* __restrict__ Bdl,
               const bf16* __restrict__ Bhh, const bf16* __restrict__ Bhl,
               bf16* __restrict__ Ch, bf16* __restrict__ Cl,
               const float* __restrict__ colsum) {
    extern __shared__ __align__(16) bf16 smp[];
    const int z = blockIdx.z;
    const int xb = blockIdx.x;
    const bool inv = xb >= 2;
    const int col0 = (xb & 1) * 128;
    const int M = SEQ, lda = 512, ldb = 512, ldc = 512;
    Ah += (long)z * (500L * 512); Al += (long)z * (500L * 512);
    const bf16* Bh = (inv ? Bhh : Bdh) + (long)z * 131072L;
    const bf16* Bl = (inv ? Bhl : Bdl) + (long)z * 131072L;
    const long coff = (long)z * (500L * 512) + (inv ? 256 : 0);
    const int row0 = blockIdx.y * 128;
    const int tid = threadIdx.x, lane = tid & 31, wid = tid >> 5;
    const int wm0 = (wid & 3) * 32, wn0 = (wid >> 2) * 64;

    const int r = tid >> 1;
    const int c0 = (tid & 1) * 2;
    int arow = row0 + r; if (arow >= M) arow = M - 1;
    int brow = col0 + r;
    const char* pAh = (const char*)(Ah + (long)arow * lda);
    const char* pAl = (const char*)(Al + (long)arow * lda);
    const char* pBh = (const char*)(Bh + (long)brow * ldb);
    const char* pBl = (const char*)(Bl + (long)brow * ldb);
    const uint32_t dst0 = smem_u32(smp) + (uint32_t)(r * 80 + c0 * 16);
    const int NIT = 512 >> 5;

    auto issue = [&](int it) {
        const uint32_t base = dst0 + (uint32_t)(it & 1) * STG_B;
        const int k0 = it << 5;
        #pragma unroll
        for (int cc = 0; cc < 2; ++cc) {
            long go = (long)(k0 + (c0 + cc) * 8) * 2;
            cpa16(base + cc * 16,         pAh + go, 16);
            cpa16(base + 10240 + cc * 16, pAl + go, 16);
            cpa16(base + 20480 + cc * 16, pBh + go, 16);
            cpa16(base + 30720 + cc * 16, pBl + go, 16);
        }
        CP_COMMIT();
    };

    float c[2][8][4];
    #pragma unroll
    for (int a = 0; a < 2; ++a)
        #pragma unroll
        for (int b = 0; b < 8; ++b)
            #pragma unroll
            for (int d = 0; d < 4; ++d) c[a][b][d] = 0.f;

    issue(0); issue(1);
    for (int it = 0; it < NIT; ++it) {
        CP_WAIT1();
        __syncthreads();
        const bf16* s0 = smp + (size_t)(it & 1) * (STG_B / 2);
        const bf16* s1 = s0 + 5120;
        const bf16* s2 = s0 + 10240;
        const bf16* s3 = s0 + 15360;
        #pragma unroll
        for (int kk = 0; kk < 2; ++kk) {
            uint32_t ah[2][4], al[2][4];
            #pragma unroll
            for (int mt = 0; mt < 2; ++mt) {
                int ra = wm0 + mt * 16 + (lane & 15);
                int ca = kk * 16 + ((lane >> 4) << 3);
                LDSM4(ah[mt], smem_u32(s0 + ra * 40 + ca));
                LDSM4(al[mt], smem_u32(s1 + ra * 40 + ca));
            }
            #pragma unroll
            for (int nt2 = 0; nt2 < 4; ++nt2) {
                int rb = wn0 + nt2 * 16 + (lane & 7) + ((lane >> 4) << 3);
                int cb2 = kk * 16 + (((lane >> 3) & 1) << 3);
                uint32_t bh[4], bl[4];
                LDSM4(bh, smem_u32(s2 + rb * 40 + cb2));
                LDSM4(bl, smem_u32(s3 + rb * 40 + cb2));
                #pragma unroll
                for (int mt = 0; mt < 2; ++mt)
                    #pragma unroll
                    for (int hh = 0; hh < 2; ++hh) {
                        float* cc = c[mt][nt2 * 2 + hh];
                        MMA_BF16(cc, ah[mt], bh[hh * 2], bh[hh * 2 + 1]);
                        MMA_BF16(cc, al[mt], bh[hh * 2], bh[hh * 2 + 1]);
                        MMA_BF16(cc, ah[mt], bl[hh * 2], bl[hh * 2 + 1]);
                    }
            }
        }
        __syncthreads();
        if (it + 2 < NIT) issue(it + 2);
        else CP_COMMIT();
    }

    const int g = lane >> 2, tg = lane & 3;
    #pragma unroll
    for (int mt = 0; mt < 2; ++mt)
        #pragma unroll
        for (int nt = 0; nt < 8; ++nt) {
            int m0 = row0 + wm0 + mt * 16 + g;
            int n0 = col0 + wn0 + nt * 8 + tg * 2;
            float v0 = c[mt][nt][0], v1 = c[mt][nt][1];
            float v2 = c[mt][nt][2], v3 = c[mt][nt][3];
            if (inv) {
                float cs0 = colsum[z * 256 + n0], cs1 = colsum[z * 256 + n0 + 1];
                v0 = cs0 - v0; v1 = cs1 - v1; v2 = cs0 - v2; v3 = cs1 - v3;
            }
            bf162 h01, l01, h23, l23;
            split2(v0, v1, h01, l01);
            split2(v2, v3, h23, l23);
            if (m0 < M) {
                *(bf162*)&Ch[coff + (long)m0 * ldc + n0] = h01;
                *(bf162*)&Cl[coff + (long)m0 * ldc + n0] = l01;
            }
            if (m0 + 8 < M) {
                *(bf162*)&Ch[coff + (long)(m0 + 8) * ldc + n0] = h23;
                *(bf162*)&Cl[coff + (long)(m0 + 8) * ldc + n0] = l23;
            }
        }
}

// ---------------- GRU recurrence: cluster-of-8 persistent scan ----------------
#define GRU_SMEM_FLOATS (96 * 260 + 96 + 2 * 1024 + 96 * 4)
#define GRU_SMEM_BYTES  (GRU_SMEM_FLOATS * 4)

__global__ void __cluster_dims__(8, 1, 1) __launch_bounds__(128, 1)
gru_kernel(const float* __restrict__ xproj,
           const float* __restrict__ whh1, const float* __restrict__ whh2,
           const float* __restrict__ bhh1, const float* __restrict__ bhh2,
           float* __restrict__ out) {
    extern __shared__ __align__(16) float sm[];
    float* Wm = sm;
    float* bias_s = sm + 96 * 260;
    float* h_s = bias_s + 96;
    float* gh_s = h_s + 2048;

    const int rank = blockIdx.x, bg = blockIdx.y, gru = blockIdx.z;
    const int tid = threadIdx.x;
    const float* whh = gru ? whh2 : whh1;
    const float* bhh = gru ? bhh2 : bhh1;

    for (int idx = tid; idx < 96 * 256; idx += 128) {
        int lr = idx >> 8, k = idx & 255;
        int grow = ((lr >> 5) << 8) + (rank << 5) + (lr & 31);
        Wm[lr * 260 + k] = whh[grow * 256 + k];
    }
    if (tid < 96)
        bias_s[tid] = bhh[((tid >> 5) << 8) + (rank << 5) + (tid & 31)];
    for (int i = tid; i < 2048; i += 128) h_s[i] = 0.f;
    __syncthreads();
    CLUSTER_SYNC_();

    const int b = tid >> 5, jj = tid & 31;
    const int jg = (rank << 5) + jj;
    const long mbase = (long)gru * MTOT + (long)bg * 4 * SEQ;
    const float* xp0 = xproj + mbase * 768;
    float* outp = out + mbase * 256;

    for (int t = 0; t < SEQ; ++t) {
        float* hc = h_s + ((t & 1) << 10);
        float* hn = h_s + (((t & 1) ^ 1) << 10);
        const float* xp = xp0 + ((long)b * SEQ + t) * 768;
        float xr = xp[jg], xz = xp[jg + 256], xn = xp[jg + 512];

        if (tid < 96) {
            const float* wrow = Wm + tid * 260;
            unsigned long long acc[4][2] = {};
            #pragma unroll 16
            for (int k = 0; k < 256; k += 4) {
                ulonglong2 w2 = *(const ulonglong2*)(wrow + k);
                #pragma unroll
                for (int bb = 0; bb < 4; ++bb) {
                    ulonglong2 h2 = *(const ulonglong2*)(hc + (bb << 8) + k);
                    FMA2(acc[bb][0], w2.x, h2.x);
                    FMA2(acc[bb][1], w2.y, h2.y);
                }
            }
            #pragma unroll
            for (int bb = 0; bb < 4; ++bb) {
                float2 p = unpackf2(acc[bb][0]);
                float2 q = unpackf2(acc[bb][1]);
                gh_s[tid * 4 + bb] = p.x + p.y + q.x + q.y + bias_s[tid];
            }
        }
        __syncthreads();
        {
            float ghr = gh_s[jj * 4 + b];
            float ghz = gh_s[(32 + jj) * 4 + b];
            float ghn = gh_s[(64 + jj) * 4 + b];
            float rr = 1.f / (1.f + __expf(-(xr + ghr)));
            float zz = 1.f / (1.f + __expf(-(xz + ghz)));
            float nn = tanhf(xn + rr * ghn);
            float hnew = (1.f - zz) * nn + zz * hc[(b << 8) + jg];
            outp[((long)b * SEQ + t) * 256 + jg] = hnew;
            unsigned laddr = smem_u32(hn + (b << 8) + jg);
            unsigned hbits = __float_as_uint(hnew);
            #pragma unroll
            for (int rd = 0; rd < 8; ++rd) {
                unsigned raddr;
                asm volatile("mapa.shared::cluster.u32 %0, %1, %2;" : "=r"(raddr) : "r"(laddr), "r"(rd));
                asm volatile("st.shared::cluster.b32 [%0], %1;" :: "r"(raddr), "r"(hbits) : "memory");
            }
        }
        CLUSTER_SYNC_();
    }
}

// ---------------- softmax rows of 500 -> split bf16 planes ----------------
__global__ void softmax_kernel(const float* __restrict__ scores,
                               bf16* __restrict__ ah, bf16* __restrict__ al) {
    __shared__ float red[8];
    const float* p = scores + (long)blockIdx.x * 512;
    int tid = threadIdx.x;
    float v1 = (tid < 500) ? p[tid] : -1e30f;
    float v2 = (tid + 256 < 500) ? p[tid + 256] : -1e30f;
    float m = fmaxf(v1, v2);
    #pragma unroll
    for (int o = 16; o; o >>= 1) m = fmaxf(m, __shfl_xor_sync(~0u, m, o));
    if ((tid & 31) == 0) red[tid >> 5] = m;
    __syncthreads();
    if (tid == 0) {
        float mm = red[0];
        #pragma unroll
        for (int i = 1; i < 8; ++i) mm = fmaxf(mm, red[i]);
        red[0] = mm;
    }
    __syncthreads();
    m = red[0];
    __syncthreads();
    float e1 = (tid < 500) ? __expf(v1 - m) : 0.f;
    float e2 = (tid + 256 < 500) ? __expf(v2 - m) : 0.f;
    float s = e1 + e2;
    #pragma unroll
    for (int o = 16; o; o >>= 1) s += __shfl_xor_sync(~0u, s, o);
    if ((tid & 31) == 0) red[tid >> 5] = s;
    __syncthreads();
    if (tid == 0) {
        float ss = 0.f;
        #pragma unroll
        for (int i = 0; i < 8; ++i) ss += red[i];
        red[0] = ss;
    }
    __syncthreads();
    float inv = 1.f / red[0];
    float a1 = e1 * inv, a2 = e2 * inv;
    long o1 = (long)blockIdx.x * 512 + tid;
    bf16 h1 = __float2bfloat16(a1);
    ah[o1] = h1;
    al[o1] = __float2bfloat16(a1 - __bfloat162float(h1));
    bf16 h2 = __float2bfloat16(a2);
    ah[o1 + 256] = h2;
    al[o1 + 256] = __float2bfloat16(a2 - __bfloat162float(h2));
}

__global__ void colsum_kernel(const float* __restrict__ outh, float* __restrict__ cs) {
    int b = blockIdx.x, j = threadIdx.x;
    const float* p = outh + (long)b * SEQ * 256 + j;
    float s = 0.f;
    for (int t = 0; t < SEQ; ++t) s += p[(long)t * 256];
    cs[b * 256 + j] = s;
}

// ---------------- host ----------------
static void launch_mm(int outk,
                      const bf16* Ah, const bf16* Al, const bf16* Bh, const bf16* Bl,
                      float* C, bf16* Ch, bf16* Cl, const float* bias, long sBias,
                      int M, int N, int K, int lda, int ldb, int ldc,
                      long sA, long sB, long sC, int batch) {
    dim3 grid((N + 127) / 128, (M + 127) / 128, batch);
    if (outk == 0)
        mma_gemm<0><<<grid, 256, MMA_SMEM>>>(Ah, Al, Bh, Bl, C, Ch, Cl, bias, sBias, M, N, K, lda, ldb, ldc, sA, sB, sC);
    else
        mma_gemm<1><<<grid, 256, MMA_SMEM>>>(Ah, Al, Bh, Bl, C, Ch, Cl, bias, sBias, M, N, K, lda, ldb, ldc, sA, sB, sC);
}
static void split_buf(const float* s, bf16* h, bf16* l, long n) {
    long n4 = n >> 2;
    split4_kernel<<<(unsigned)((n4 + 255) / 256), 256>>>((const float4*)s, h, l, n4);
}

extern "C" void kernel_launch(void* const* d_in, const int* in_sizes, int n_in,
                              void* d_out, int out_size) {
    const float* x     = (const float*)d_in[0];
    const float* qh    = (const float*)d_in[1];
    const float* qd    = (const float*)d_in[2];
    const float* g1wih = (const float*)d_in[3];
    const float* g1whh = (const float*)d_in[4];
    const float* g1bih = (const float*)d_in[5];
    const float* g1bhh = (const float*)d_in[6];
    const float* g2wih = (const float*)d_in[7];
    const float* g2whh = (const float*)d_in[8];
    const float* g2bih = (const float*)d_in[9];
    const float* g2bhh = (const float*)d_in[10];
    const float* fccw  = (const float*)d_in[11];
    const float* fccb  = (const float*)d_in[12];
    const float* fctw  = (const float*)d_in[13];
    const float* fctb  = (const float*)d_in[14];
    const float* fcew  = (const float*)d_in[15];
    const float* fceb  = (const float*)d_in[16];
    float* out = (float*)d_out;

    bf16 *xh, *xl, *qTh, *qTl, *wh, *wl, *xeh, *xel, *gh, *gl, *gTh, *gTl, *ah, *al, *ensh, *ensl;
    float *xproj, *gout, *attn, *colsum, *biasL, *biasP;
    cudaGetSymbolAddress((void**)&xh, g_xh);   cudaGetSymbolAddress((void**)&xl, g_xl);
    cudaGetSymbolAddress((void**)&qTh, g_qTh); cudaGetSymbolAddress((void**)&qTl, g_qTl);
    cudaGetSymbolAddress((void**)&wh, g_wh);   cudaGetSymbolAddress((void**)&wl, g_wl);
    cudaGetSymbolAddress((void**)&xeh, g_xeh); cudaGetSymbolAddress((void**)&xel, g_xel);
    cudaGetSymbolAddress((void**)&gh, g_gh);   cudaGetSymbolAddress((void**)&gl, g_gl);
    cudaGetSymbolAddress((void**)&gTh, g_gTh); cudaGetSymbolAddress((void**)&gTl, g_gTl);
    cudaGetSymbolAddress((void**)&ah, g_ah);   cudaGetSymbolAddress((void**)&al, g_al);
    cudaGetSymbolAddress((void**)&ensh, g_ensh); cudaGetSymbolAddress((void**)&ensl, g_ensl);
    cudaGetSymbolAddress((void**)&xproj, g_xproj);
    cudaGetSymbolAddress((void**)&gout, g_out);
    cudaGetSymbolAddress((void**)&attn, g_attn);
    cudaGetSymbolAddress((void**)&colsum, g_colsum);
    cudaGetSymbolAddress((void**)&biasL, g_biasL);
    cudaGetSymbolAddress((void**)&biasP, g_biasP);

    cudaFuncSetAttribute(mma_gemm<0>, cudaFuncAttributeMaxDynamicSharedMemorySize, MMA_SMEM);
    cudaFuncSetAttribute(mma_gemm<1>, cudaFuncAttributeMaxDynamicSharedMemorySize, MMA_SMEM);
    cudaFuncSetAttribute(mma_apply,   cudaFuncAttributeMaxDynamicSharedMemorySize, MMA_SMEM);
    cudaFuncSetAttribute(gru_kernel,  cudaFuncAttributeMaxDynamicSharedMemorySize, GRU_SMEM_BYTES);

    // 1. operand splits + bias concats
    split_buf(x, xh, xl, (long)MTOT * KX);
    packqT_kernel<<<dim3((KX + 31) / 32, 16), dim3(32, 8)>>>(qh, qd, qTh, qTl);
    split_buf(g1wih, wh + WOFF_W1, wl + WOFF_W1, 768 * 256);
    split_buf(g2wih, wh + WOFF_W2, wl + WOFF_W2, 768 * 256);
    split_buf(fccw,  wh + WOFF_WC, wl + WOFF_WC, (long)NUM_Q * 256);
    split_buf(fctw,  wh + WOFF_WT, wl + WOFF_WT, (long)NUM_Q * 256);
    split_buf(fcew,  wh + WOFF_WE, wl + WOFF_WE, (long)NUM_Q * 512);
    cat2_kernel<<<(2 * 768 + 255) / 256, 256>>>(g1bih, g2bih, biasP, 768);
    cat2_kernel<<<(2 * NUM_Q + 255) / 256, 256>>>(fccb, fctb, biasL, NUM_Q);

    // 2. embeddings -> xe split planes [16000][512]
    launch_mm(1, xh, xl, qTh, qTl, nullptr, xeh, xel, nullptr, 0,
              MTOT, 512, KX, KX, KX, 512, 0, 0, 0, 1);

    // 3. input projections fused over both GRUs: [2][16000][768] fp32
    launch_mm(0, xeh, xel, wh + WOFF_W1, wl + WOFF_W1, xproj, nullptr, nullptr, biasP, 768,
              MTOT, 768, 256, 512, 256, 768, 256, 196608, (long)MTOT * 768, 2);

    // 4. GRU
    gru_kernel<<<dim3(8, 8, 2), 128, GRU_SMEM_BYTES>>>(xproj, g1whh, g2whh, g1bhh, g2bhh, gout);

    // 5. split + transpose-split hidden states
    split_buf(gout, gh, gl, 2L * MTOT * 256);
    transpSplit_kernel<<<dim3(16, 8, 64), dim3(32, 8)>>>(gout, gTh, gTl);

    const bf16 *ghh = gh, *ghl = gl;
    const bf16 *gdh = gh + (long)MTOT * 256, *gdl = gl + (long)MTOT * 256;

    // 6. per-branch logits fused: z=0 -> logit_c, z=1 -> logit_t
    launch_mm(0, ghh, ghl, wh + WOFF_WC, wl + WOFF_WC, out, nullptr, nullptr, biasL, NUM_Q,
              MTOT, NUM_Q, 256, 256, 256, NUM_Q, (long)MTOT * 256, 768000, 48000000L, 2);

    // 7. colsum of out_h
    colsum_kernel<<<BATCH, 256>>>(gout, colsum);

    // 8. attention scores (batched) -> fp32 attn ld 512
    launch_mm(0, ghh, ghl, gdh, gdl, attn, nullptr, nullptr, nullptr, 0,
              SEQ, SEQ, 256, 256, 256, 512, 500L * 256, 500L * 256, 500L * 512, BATCH);

    // 9. softmax -> attn split planes
    softmax_kernel<<<MTOT, 256>>>(attn, ah, al);

    // 10. fused attention apply (both halves of ens in one launch)
    mma_apply<<<dim3(4, 4, BATCH), 256, MMA_SMEM>>>(
        ah, al, gTh + 4194304L, gTl + 4194304L, gTh, gTl, ensh, ensl, colsum);

    // 11. ensemble logits
    launch_mm(0, ensh, ensl, wh + WOFF_WE, wl + WOFF_WE, out + 96000000L, nullptr, nullptr, fceb, 0,
              MTOT, NUM_Q, 512, 512, 512, NUM_Q, 0, 0, 0, 1);
}

// round 16
// speedup vs baseline: 1.5421x; 1.5421x over previous
#include <cuda_runtime.h>
#include <cuda_bf16.h>
#include <cstdint>

#define NUM_Q 3000
#define BATCH 32
#define SEQ 500
#define MTOT (BATCH * SEQ)
#define KX (2 * NUM_Q)

typedef __nv_bfloat16 bf16;
typedef __nv_bfloat162 bf162;

// ---------------- scratch (bf16 hi/lo planes) ----------------
__device__ __align__(256) bf16 g_xh[(size_t)MTOT * KX + 64];
__device__ __align__(256) bf16 g_xl[(size_t)MTOT * KX + 64];
__device__ __align__(256) bf16 g_qTh[512 * KX + 64];
__device__ __align__(256) bf16 g_qTl[512 * KX + 64];
__device__ __align__(256) bf16 g_wh[3465216];
__device__ __align__(256) bf16 g_wl[3465216];
__device__ __align__(256) bf16 g_xeh[(size_t)MTOT * 512];
__device__ __align__(256) bf16 g_xel[(size_t)MTOT * 512];
__device__ __align__(256) bf16 g_gh[2ll * MTOT * 256];
__device__ __align__(256) bf16 g_gl[2ll * MTOT * 256];
__device__ __align__(256) bf16 g_gTh[2ll * 32 * 256 * 512];
__device__ __align__(256) bf16 g_gTl[2ll * 32 * 256 * 512];
__device__ __align__(256) bf16 g_ah[(size_t)MTOT * 512];
__device__ __align__(256) bf16 g_al[(size_t)MTOT * 512];
__device__ __align__(256) bf16 g_ensh[(size_t)MTOT * 512];
__device__ __align__(256) bf16 g_ensl[(size_t)MTOT * 512];
__device__ float g_xproj[2ll * MTOT * 768];
__device__ float g_out[2ll * MTOT * 256];
__device__ float g_attn[(size_t)MTOT * 512];
__device__ float g_colsum[BATCH * 256];
__device__ float g_biasL[2 * NUM_Q];     // fccb | fctb
__device__ float g_biasP[2 * 768];       // g1bih | g2bih

#define WOFF_W1 0
#define WOFF_W2 196608
#define WOFF_WC 393216
#define WOFF_WT 1161216
#define WOFF_WE 1929216

// ---------------- helpers ----------------
__device__ __forceinline__ unsigned long long dupf2(float x) {
    unsigned long long r; asm("mov.b64 %0, {%1, %1};" : "=l"(r) : "f"(x)); return r;
}
__device__ __forceinline__ float2 unpackf2(unsigned long long v) {
    float2 f; asm("mov.b64 {%0, %1}, %2;" : "=f"(f.x), "=f"(f.y) : "l"(v)); return f;
}
#define FMA2(d, a, b) asm("fma.rn.f32x2 %0, %1, %2, %0;" : "+l"(d) : "l"(a), "l"(b))

__device__ __forceinline__ unsigned smem_u32(const void* p) {
    unsigned r;
    asm("{ .reg .u64 t; cvta.to.shared.u64 t, %1; cvt.u32.u64 %0, t; }" : "=r"(r) : "l"(p));
    return r;
}
#define CLUSTER_SYNC_() do { \
    asm volatile("barrier.cluster.arrive.aligned;" ::: "memory"); \
    asm volatile("barrier.cluster.wait.aligned;"   ::: "memory"); } while (0)

#define LDSM4(r, addr) asm volatile( \
    "ldmatrix.sync.aligned.m8n8.x4.shared.b16 {%0,%1,%2,%3}, [%4];" \
    : "=r"((r)[0]), "=r"((r)[1]), "=r"((r)[2]), "=r"((r)[3]) : "r"(addr))

#define MMA_BF16(c, a, b0, b1) asm volatile( \
    "mma.sync.aligned.m16n8k16.row.col.f32.bf16.bf16.f32 " \
    "{%0,%1,%2,%3}, {%4,%5,%6,%7}, {%8,%9}, {%0,%1,%2,%3};" \
    : "+f"((c)[0]), "+f"((c)[1]), "+f"((c)[2]), "+f"((c)[3]) \
    : "r"((a)[0]), "r"((a)[1]), "r"((a)[2]), "r"((a)[3]), "r"(b0), "r"(b1))

__device__ __forceinline__ void cpa16(uint32_t dst, const void* src, unsigned bytes) {
    asm volatile("cp.async.cg.shared.global [%0], [%1], 16, %2;"
                 :: "r"(dst), "l"(src), "r"(bytes) : "memory");
}
#define CP_COMMIT() asm volatile("cp.async.commit_group;" ::: "memory")
#define CP_WAIT1()  asm volatile("cp.async.wait_group 1;" ::: "memory")

__device__ __forceinline__ void split2(float a, float b, bf162& h, bf162& l) {
    h = __floats2bfloat162_rn(a, b);
    float2 f = __bfloat1622float2(h);
    l = __floats2bfloat162_rn(a - f.x, b - f.y);
}

// ---------------- generic fp32 -> bf16 hi/lo split ----------------
__global__ void split4_kernel(const float4* __restrict__ s,
                              bf16* __restrict__ h, bf16* __restrict__ l, long n4) {
    long i = (long)blockIdx.x * 256 + threadIdx.x;
    if (i < n4) {
        float4 v = s[i];
        bf162 h01, l01, h23, l23;
        split2(v.x, v.y, h01, l01);
        split2(v.z, v.w, h23, l23);
        ((bf162*)h)[i * 2] = h01;     ((bf162*)h)[i * 2 + 1] = h23;
        ((bf162*)l)[i * 2] = l01;     ((bf162*)l)[i * 2 + 1] = l23;
    }
}

// ---------------- concat two bias vectors ----------------
__global__ void cat2_kernel(const float* __restrict__ a, const float* __restrict__ b,
                            float* __restrict__ d, int n) {
    int i = blockIdx.x * 256 + threadIdx.x;
    if (i < n) d[i] = a[i];
    else if (i < 2 * n) d[i] = b[i - n];
}

// ---------------- pack question tables transposed + split ----------------
__global__ void packqT_kernel(const float* __restrict__ qh, const float* __restrict__ qd,
                              bf16* __restrict__ th, bf16* __restrict__ tl) {
    __shared__ float t[32][33];
    int kb = blockIdx.x * 32, cb = blockIdx.y * 32;
    const float* src = (cb < 256) ? qh : qd;
    int cc0 = cb & 255;
    int x = threadIdx.x, y = threadIdx.y;
    for (int yy = y; yy < 32; yy += 8) {
        int k = kb + yy;
        t[yy][x] = (k < KX) ? src[(long)k * 256 + cc0 + x] : 0.f;
    }
    __syncthreads();
    if (kb + x < KX)
        for (int yy = y; yy < 32; yy += 8) {
            float v = t[x][yy];
            bf16 hv = __float2bfloat16(v);
            th[(long)(cb + yy) * KX + kb + x] = hv;
            tl[(long)(cb + yy) * KX + kb + x] = __float2bfloat16(v - __bfloat162float(hv));
        }
}

// ---------------- transpose + split GRU outputs ----------------
__global__ void transpSplit_kernel(const float* __restrict__ g,
                                   bf16* __restrict__ th, bf16* __restrict__ tl) {
    __shared__ float tile[32][33];
    int gb = blockIdx.z;
    int t0 = blockIdx.x * 32, j0 = blockIdx.y * 32;
    const float* src = g + (long)gb * SEQ * 256;
    int x = threadIdx.x, y = threadIdx.y;
    for (int yy = y; yy < 32; yy += 8) {
        int t = t0 + yy;
        tile[yy][x] = (t < SEQ) ? src[(long)t * 256 + j0 + x] : 0.f;
    }
    __syncthreads();
    for (int yy = y; yy < 32; yy += 8) {
        long o = (long)(gb * 256 + j0 + yy) * 512 + t0 + x;
        float v = tile[x][yy];
        bf16 hv = __float2bfloat16(v);
        th[o] = hv;
        tl[o] = __float2bfloat16(v - __bfloat162float(hv));
    }
}

// ---------------- pipelined bf16-split tensor-core NT GEMM ----------------
// C = (Ah+Al)@(Bh+Bl)^T dropping Al*Bl. 2-stage cp.async double buffer, 2 CTAs/SM.
// OUT=0: fp32 C (+bias, bias += z*sBias). OUT=1: split bf16 Ch/Cl.
#define PIPE 2
#define STG_B 40960
#define MMA_SMEM (PIPE * STG_B)

template <int OUT>
__global__ __launch_bounds__(256, 2)
void mma_gemm(const bf16* __restrict__ Ah, const bf16* __restrict__ Al,
              const bf16* __restrict__ Bh, const bf16* __restrict__ Bl,
              float* __restrict__ C, bf16* __restrict__ Ch, bf16* __restrict__ Cl,
              const float* __restrict__ bias, long sBias,
              int M, int N, int K, int lda, int ldb, int ldc,
              long sA, long sB, long sC) {
    extern __shared__ __align__(16) bf16 smp[];
    const int z = blockIdx.z;
    Ah += (long)z * sA; Al += (long)z * sA;
    Bh += (long)z * sB; Bl += (long)z * sB;
    if (bias) bias += (long)z * sBias;
    const long coff = (long)z * sC;
    const int row0 = blockIdx.y * 128, col0 = blockIdx.x * 128;
    const int tid = threadIdx.x, lane = tid & 31, wid = tid >> 5;
    const int wm0 = (wid & 3) * 32, wn0 = (wid >> 2) * 64;

    const int r = tid >> 1;
    const int c0 = (tid & 1) * 2;
    int arow = row0 + r; if (arow >= M) arow = M - 1;
    int brow = col0 + r; if (brow >= N) brow = N - 1;
    const char* pAh = (const char*)(Ah + (long)arow * lda);
    const char* pAl = (const char*)(Al + (long)arow * lda);
    const char* pBh = (const char*)(Bh + (long)brow * ldb);
    const char* pBl = (const char*)(Bl + (long)brow * ldb);
    const uint32_t dst0 = smem_u32(smp) + (uint32_t)(r * 80 + c0 * 16);
    const int NIT = (K + 31) >> 5;

    auto issue = [&](int it) {
        const uint32_t base = dst0 + (uint32_t)(it & 1) * STG_B;
        const int k0 = it << 5;
        #pragma unroll
        for (int cc = 0; cc < 2; ++cc) {
            int kh = k0 + (c0 + cc) * 8;
            int rem = K - kh;
            unsigned bytes = rem >= 8 ? 16u : (rem > 0 ? (unsigned)(rem * 2) : 0u);
            long go = (long)kh * 2;
            cpa16(base + cc * 16,         pAh + go, bytes);
            cpa16(base + 10240 + cc * 16, pAl + go, bytes);
            cpa16(base + 20480 + cc * 16, pBh + go, bytes);
            cpa16(base + 30720 + cc * 16, pBl + go, bytes);
        }
        CP_COMMIT();
    };

    float c[2][8][4];
    #pragma unroll
    for (int a = 0; a < 2; ++a)
        #pragma unroll
        for (int b = 0; b < 8; ++b)
            #pragma unroll
            for (int d = 0; d < 4; ++d) c[a][b][d] = 0.f;

    issue(0); issue(1);

    for (int it = 0; it < NIT; ++it) {
        CP_WAIT1();
        __syncthreads();

        const bf16* s0 = smp + (size_t)(it & 1) * (STG_B / 2);
        const bf16* s1 = s0 + 5120;
        const bf16* s2 = s0 + 10240;
        const bf16* s3 = s0 + 15360;

        #pragma unroll
        for (int kk = 0; kk < 2; ++kk) {
            uint32_t ah[2][4], al[2][4];
            #pragma unroll
            for (int mt = 0; mt < 2; ++mt) {
                int ra = wm0 + mt * 16 + (lane & 15);
                int ca = kk * 16 + ((lane >> 4) << 3);
                LDSM4(ah[mt], smem_u32(s0 + ra * 40 + ca));
                LDSM4(al[mt], smem_u32(s1 + ra * 40 + ca));
            }
            #pragma unroll
            for (int nt2 = 0; nt2 < 4; ++nt2) {
                int rb = wn0 + nt2 * 16 + (lane & 7) + ((lane >> 4) << 3);
                int cb2 = kk * 16 + (((lane >> 3) & 1) << 3);
                uint32_t bh[4], bl[4];
                LDSM4(bh, smem_u32(s2 + rb * 40 + cb2));
                LDSM4(bl, smem_u32(s3 + rb * 40 + cb2));
                #pragma unroll
                for (int mt = 0; mt < 2; ++mt)
                    #pragma unroll
                    for (int hh = 0; hh < 2; ++hh) {
                        float* cc = c[mt][nt2 * 2 + hh];
                        MMA_BF16(cc, ah[mt], bh[hh * 2], bh[hh * 2 + 1]);
                        MMA_BF16(cc, al[mt], bh[hh * 2], bh[hh * 2 + 1]);
                        MMA_BF16(cc, ah[mt], bl[hh * 2], bl[hh * 2 + 1]);
                    }
            }
        }
        __syncthreads();
        if (it + 2 < NIT) issue(it + 2);
        else CP_COMMIT();
    }

    const int g = lane >> 2, tg = lane & 3;
    #pragma unroll
    for (int mt = 0; mt < 2; ++mt)
        #pragma unroll
        for (int nt = 0; nt < 8; ++nt) {
            int m0 = row0 + wm0 + mt * 16 + g;
            int n0 = col0 + wn0 + nt * 8 + tg * 2;
            if (n0 >= N) continue;
            float v0 = c[mt][nt][0], v1 = c[mt][nt][1];
            float v2 = c[mt][nt][2], v3 = c[mt][nt][3];
            if (OUT == 0) {
                float b0 = bias ? bias[n0] : 0.f;
                float b1 = bias ? bias[n0 + 1] : 0.f;
                if (m0 < M)
                    *(float2*)&C[coff + (long)m0 * ldc + n0] = make_float2(v0 + b0, v1 + b1);
                if (m0 + 8 < M)
                    *(float2*)&C[coff + (long)(m0 + 8) * ldc + n0] = make_float2(v2 + b0, v3 + b1);
            } else {
                bf162 h01, l01, h23, l23;
                split2(v0, v1, h01, l01);
                split2(v2, v3, h23, l23);
                if (m0 < M) {
                    *(bf162*)&Ch[coff + (long)m0 * ldc + n0] = h01;
                    *(bf162*)&Cl[coff + (long)m0 * ldc + n0] = l01;
                }
                if (m0 + 8 < M) {
                    *(bf162*)&Ch[coff + (long)(m0 + 8) * ldc + n0] = h23;
                    *(bf162*)&Cl[coff + (long)(m0 + 8) * ldc + n0] = l23;
                }
            }
        }
}

// ---------------- fused attention-apply: grid.x 0-1 -> attn@out_d ; 2-3 -> colsum - attn@out_h ----------------
__global__ __launch_bounds__(256, 2)
void mma_apply(const bf16* __restrict__ Ah, const bf16* __restrict__ Al,
               const bf16* __restrict__ Bdh, const bf16* __restrict__ Bdl,
               const bf16* __restrict__ Bhh, const bf16* __restrict__ Bhl,
               bf16* __restrict__ Ch, bf16* __restrict__ Cl,
               const float* __restrict__ colsum) {
    extern __shared__ __align__(16) bf16 smp[];
    const int z = blockIdx.z;
    const int xb = blockIdx.x;
    const bool inv = xb >= 2;
    const int col0 = (xb & 1) * 128;
    const int M = SEQ, lda = 512, ldb = 512, ldc = 512;
    Ah += (long)z * (500L * 512); Al += (long)z * (500L * 512);
    const bf16* Bh = (inv ? Bhh : Bdh) + (long)z * 131072L;
    const bf16* Bl = (inv ? Bhl : Bdl) + (long)z * 131072L;
    const long coff = (long)z * (500L * 512) + (inv ? 256 : 0);
    const int row0 = blockIdx.y * 128;
    const int tid = threadIdx.x, lane = tid & 31, wid = tid >> 5;
    const int wm0 = (wid & 3) * 32, wn0 = (wid >> 2) * 64;

    const int r = tid >> 1;
    const int c0 = (tid & 1) * 2;
    int arow = row0 + r; if (arow >= M) arow = M - 1;
    int brow = col0 + r;
    const char* pAh = (const char*)(Ah + (long)arow * lda);
    const char* pAl = (const char*)(Al + (long)arow * lda);
    const char* pBh = (const char*)(Bh + (long)brow * ldb);
    const char* pBl = (const char*)(Bl + (long)brow * ldb);
    const uint32_t dst0 = smem_u32(smp) + (uint32_t)(r * 80 + c0 * 16);
    const int NIT = 512 >> 5;

    auto issue = [&](int it) {
        const uint32_t base = dst0 + (uint32_t)(it & 1) * STG_B;
        const int k0 = it << 5;
        #pragma unroll
        for (int cc = 0; cc < 2; ++cc) {
            long go = (long)(k0 + (c0 + cc) * 8) * 2;
            cpa16(base + cc * 16,         pAh + go, 16);
            cpa16(base + 10240 + cc * 16, pAl + go, 16);
            cpa16(base + 20480 + cc * 16, pBh + go, 16);
            cpa16(base + 30720 + cc * 16, pBl + go, 16);
        }
        CP_COMMIT();
    };

    float c[2][8][4];
    #pragma unroll
    for (int a = 0; a < 2; ++a)
        #pragma unroll
        for (int b = 0; b < 8; ++b)
            #pragma unroll
            for (int d = 0; d < 4; ++d) c[a][b][d] = 0.f;

    issue(0); issue(1);
    for (int it = 0; it < NIT; ++it) {
        CP_WAIT1();
        __syncthreads();
        const bf16* s0 = smp + (size_t)(it & 1) * (STG_B / 2);
        const bf16* s1 = s0 + 5120;
        const bf16* s2 = s0 + 10240;
        const bf16* s3 = s0 + 15360;
        #pragma unroll
        for (int kk = 0; kk < 2; ++kk) {
            uint32_t ah[2][4], al[2][4];
            #pragma unroll
            for (int mt = 0; mt < 2; ++mt) {
                int ra = wm0 + mt * 16 + (lane & 15);
                int ca = kk * 16 + ((lane >> 4) << 3);
                LDSM4(ah[mt], smem_u32(s0 + ra * 40 + ca));
                LDSM4(al[mt], smem_u32(s1 + ra * 40 + ca));
            }
            #pragma unroll
            for (int nt2 = 0; nt2 < 4; ++nt2) {
                int rb = wn0 + nt2 * 16 + (lane & 7) + ((lane >> 4) << 3);
                int cb2 = kk * 16 + (((lane >> 3) & 1) << 3);
                uint32_t bh[4], bl[4];
                LDSM4(bh, smem_u32(s2 + rb * 40 + cb2));
                LDSM4(bl, smem_u32(s3 + rb * 40 + cb2));
                #pragma unroll
                for (int mt = 0; mt < 2; ++mt)
                    #pragma unroll
                    for (int hh = 0; hh < 2; ++hh) {
                        float* cc = c[mt][nt2 * 2 + hh];
                        MMA_BF16(cc, ah[mt], bh[hh * 2], bh[hh * 2 + 1]);
                        MMA_BF16(cc, al[mt], bh[hh * 2], bh[hh * 2 + 1]);
                        MMA_BF16(cc, ah[mt], bl[hh * 2], bl[hh * 2 + 1]);
                    }
            }
        }
        __syncthreads();
        if (it + 2 < NIT) issue(it + 2);
        else CP_COMMIT();
    }

    const int g = lane >> 2, tg = lane & 3;
    #pragma unroll
    for (int mt = 0; mt < 2; ++mt)
        #pragma unroll
        for (int nt = 0; nt < 8; ++nt) {
            int m0 = row0 + wm0 + mt * 16 + g;
            int n0 = col0 + wn0 + nt * 8 + tg * 2;
            float v0 = c[mt][nt][0], v1 = c[mt][nt][1];
            float v2 = c[mt][nt][2], v3 = c[mt][nt][3];
            if (inv) {
                float cs0 = colsum[z * 256 + n0], cs1 = colsum[z * 256 + n0 + 1];
                v0 = cs0 - v0; v1 = cs1 - v1; v2 = cs0 - v2; v3 = cs1 - v3;
            }
            bf162 h01, l01, h23, l23;
            split2(v0, v1, h01, l01);
            split2(v2, v3, h23, l23);
            if (m0 < M) {
                *(bf162*)&Ch[coff + (long)m0 * ldc + n0] = h01;
                *(bf162*)&Cl[coff + (long)m0 * ldc + n0] = l01;
            }
            if (m0 + 8 < M) {
                *(bf162*)&Ch[coff + (long)(m0 + 8) * ldc + n0] = h23;
                *(bf162*)&Cl[coff + (long)(m0 + 8) * ldc + n0] = l23;
            }
        }
}

// ---------------- GRU recurrence: cluster-of-8 persistent scan ----------------
#define GRU_SMEM_FLOATS (96 * 260 + 96 + 2 * 1024 + 96 * 4)
#define GRU_SMEM_BYTES  (GRU_SMEM_FLOATS * 4)

__global__ void __cluster_dims__(8, 1, 1) __launch_bounds__(128, 1)
gru_kernel(const float* __restrict__ xproj,
           const float* __restrict__ whh1, const float* __restrict__ whh2,
           const float* __restrict__ bhh1, const float* __restrict__ bhh2,
           float* __restrict__ out) {
    extern __shared__ __align__(16) float sm[];
    float* Wm = sm;
    float* bias_s = sm + 96 * 260;
    float* h_s = bias_s + 96;
    float* gh_s = h_s + 2048;

    const int rank = blockIdx.x, bg = blockIdx.y, gru = blockIdx.z;
    const int tid = threadIdx.x;
    const float* whh = gru ? whh2 : whh1;
    const float* bhh = gru ? bhh2 : bhh1;

    for (int idx = tid; idx < 96 * 256; idx += 128) {
        int lr = idx >> 8, k = idx & 255;
        int grow = ((lr >> 5) << 8) + (rank << 5) + (lr & 31);
        Wm[lr * 260 + k] = whh[grow * 256 + k];
    }
    if (tid < 96)
        bias_s[tid] = bhh[((tid >> 5) << 8) + (rank << 5) + (tid & 31)];
    for (int i = tid; i < 2048; i += 128) h_s[i] = 0.f;
    __syncthreads();
    CLUSTER_SYNC_();

    const int b = tid >> 5, jj = tid & 31;
    const int jg = (rank << 5) + jj;
    const long mbase = (long)gru * MTOT + (long)bg * 4 * SEQ;
    const float* xp0 = xproj + mbase * 768;
    float* outp = out + mbase * 256;

    for (int t = 0; t < SEQ; ++t) {
        float* hc = h_s + ((t & 1) << 10);
        float* hn = h_s + (((t & 1) ^ 1) << 10);
        const float* xp = xp0 + ((long)b * SEQ + t) * 768;
        float xr = xp[jg], xz = xp[jg + 256], xn = xp[jg + 512];

        if (tid < 96) {
            const float* wrow = Wm + tid * 260;
            unsigned long long acc[4][2] = {};
            #pragma unroll 16
            for (int k = 0; k < 256; k += 4) {
                ulonglong2 w2 = *(const ulonglong2*)(wrow + k);
                #pragma unroll
                for (int bb = 0; bb < 4; ++bb) {
                    ulonglong2 h2 = *(const ulonglong2*)(hc + (bb << 8) + k);
                    FMA2(acc[bb][0], w2.x, h2.x);
                    FMA2(acc[bb][1], w2.y, h2.y);
                }
            }
            #pragma unroll
            for (int bb = 0; bb < 4; ++bb) {
                float2 p = unpackf2(acc[bb][0]);
                float2 q = unpackf2(acc[bb][1]);
                gh_s[tid * 4 + bb] = p.x + p.y + q.x + q.y + bias_s[tid];
            }
        }
        __syncthreads();
        {
            float ghr = gh_s[jj * 4 + b];
            float ghz = gh_s[(32 + jj) * 4 + b];
            float ghn = gh_s[(64 + jj) * 4 + b];
            float rr = 1.f / (1.f + __expf(-(xr + ghr)));
            float zz = 1.f / (1.f + __expf(-(xz + ghz)));
            float nn = tanhf(xn + rr * ghn);
            float hnew = (1.f - zz) * nn + zz * hc[(b << 8) + jg];
            outp[((long)b * SEQ + t) * 256 + jg] = hnew;
            unsigned laddr = smem_u32(hn + (b << 8) + jg);
            unsigned hbits = __float_as_uint(hnew);
            #pragma unroll
            for (int rd = 0; rd < 8; ++rd) {
                unsigned raddr;
                asm volatile("mapa.shared::cluster.u32 %0, %1, %2;" : "=r"(raddr) : "r"(laddr), "r"(rd));
                asm volatile("st.shared::cluster.b32 [%0], %1;" :: "r"(raddr), "r"(hbits) : "memory");
            }
        }
        CLUSTER_SYNC_();
    }
}

// ---------------- softmax rows of 500 -> split bf16 planes ----------------
__global__ void softmax_kernel(const float* __restrict__ scores,
                               bf16* __restrict__ ah, bf16* __restrict__ al) {
    __shared__ float red[8];
    const float* p = scores + (long)blockIdx.x * 512;
    int tid = threadIdx.x;
    float v1 = (tid < 500) ? p[tid] : -1e30f;
    float v2 = (tid + 256 < 500) ? p[tid + 256] : -1e30f;
    float m = fmaxf(v1, v2);
    #pragma unroll
    for (int o = 16; o; o >>= 1) m = fmaxf(m, __shfl_xor_sync(~0u, m, o));
    if ((tid & 31) == 0) red[tid >> 5] = m;
    __syncthreads();
    if (tid == 0) {
        float mm = red[0];
        #pragma unroll
        for (int i = 1; i < 8; ++i) mm = fmaxf(mm, red[i]);
        red[0] = mm;
    }
    __syncthreads();
    m = red[0];
    __syncthreads();
    float e1 = (tid < 500) ? __expf(v1 - m) : 0.f;
    float e2 = (tid + 256 < 500) ? __expf(v2 - m) : 0.f;
    float s = e1 + e2;
    #pragma unroll
    for (int o = 16; o; o >>= 1) s += __shfl_xor_sync(~0u, s, o);
    if ((tid & 31) == 0) red[tid >> 5] = s;
    __syncthreads();
    if (tid == 0) {
        float ss = 0.f;
        #pragma unroll
        for (int i = 0; i < 8; ++i) ss += red[i];
        red[0] = ss;
    }
    __syncthreads();
    float inv = 1.f / red[0];
    float a1 = e1 * inv, a2 = e2 * inv;
    long o1 = (long)blockIdx.x * 512 + tid;
    bf16 h1 = __float2bfloat16(a1);
    ah[o1] = h1;
    al[o1] = __float2bfloat16(a1 - __bfloat162float(h1));
    bf16 h2 = __float2bfloat16(a2);
    ah[o1 + 256] = h2;
    al[o1 + 256] = __float2bfloat16(a2 - __bfloat162float(h2));
}

__global__ void colsum_kernel(const float* __restrict__ outh, float* __restrict__ cs) {
    int b = blockIdx.x, j = threadIdx.x;
    const float* p = outh + (long)b * SEQ * 256 + j;
    float s = 0.f;
    for (int t = 0; t < SEQ; ++t) s += p[(long)t * 256];
    cs[b * 256 + j] = s;
}

// ---------------- host ----------------
static void launch_mm(int outk,
                      const bf16* Ah, const bf16* Al, const bf16* Bh, const bf16* Bl,
                      float* C, bf16* Ch, bf16* Cl, const float* bias, long sBias,
                      int M, int N, int K, int lda, int ldb, int ldc,
                      long sA, long sB, long sC, int batch) {
    dim3 grid((N + 127) / 128, (M + 127) / 128, batch);
    if (outk == 0)
        mma_gemm<0><<<grid, 256, MMA_SMEM>>>(Ah, Al, Bh, Bl, C, Ch, Cl, bias, sBias, M, N, K, lda, ldb, ldc, sA, sB, sC);
    else
        mma_gemm<1><<<grid, 256, MMA_SMEM>>>(Ah, Al, Bh, Bl, C, Ch, Cl, bias, sBias, M, N, K, lda, ldb, ldc, sA, sB, sC);
}
static void split_buf(const float* s, bf16* h, bf16* l, long n) {
    long n4 = n >> 2;
    split4_kernel<<<(unsigned)((n4 + 255) / 256), 256>>>((const float4*)s, h, l, n4);
}

extern "C" void kernel_launch(void* const* d_in, const int* in_sizes, int n_in,
                              void* d_out, int out_size) {
    const float* x     = (const float*)d_in[0];
    const float* qh    = (const float*)d_in[1];
    const float* qd    = (const float*)d_in[2];
    const float* g1wih = (const float*)d_in[3];
    const float* g1whh = (const float*)d_in[4];
    const float* g1bih = (const float*)d_in[5];
    const float* g1bhh = (const float*)d_in[6];
    const float* g2wih = (const float*)d_in[7];
    const float* g2whh = (const float*)d_in[8];
    const float* g2bih = (const float*)d_in[9];
    const float* g2bhh = (const float*)d_in[10];
    const float* fccw  = (const float*)d_in[11];
    const float* fccb  = (const float*)d_in[12];
    const float* fctw  = (const float*)d_in[13];
    const float* fctb  = (const float*)d_in[14];
    const float* fcew  = (const float*)d_in[15];
    const float* fceb  = (const float*)d_in[16];
    float* out = (float*)d_out;

    bf16 *xh, *xl, *qTh, *qTl, *wh, *wl, *xeh, *xel, *gh, *gl, *gTh, *gTl, *ah, *al, *ensh, *ensl;
    float *xproj, *gout, *attn, *colsum, *biasL, *biasP;
    cudaGetSymbolAddress((void**)&xh, g_xh);   cudaGetSymbolAddress((void**)&xl, g_xl);
    cudaGetSymbolAddress((void**)&qTh, g_qTh); cudaGetSymbolAddress((void**)&qTl, g_qTl);
    cudaGetSymbolAddress((void**)&wh, g_wh);   cudaGetSymbolAddress((void**)&wl, g_wl);
    cudaGetSymbolAddress((void**)&xeh, g_xeh); cudaGetSymbolAddress((void**)&xel, g_xel);
    cudaGetSymbolAddress((void**)&gh, g_gh);   cudaGetSymbolAddress((void**)&gl, g_gl);
    cudaGetSymbolAddress((void**)&gTh, g_gTh); cudaGetSymbolAddress((void**)&gTl, g_gTl);
    cudaGetSymbolAddress((void**)&ah, g_ah);   cudaGetSymbolAddress((void**)&al, g_al);
    cudaGetSymbolAddress((void**)&ensh, g_ensh); cudaGetSymbolAddress((void**)&ensl, g_ensl);
    cudaGetSymbolAddress((void**)&xproj, g_xproj);
    cudaGetSymbolAddress((void**)&gout, g_out);
    cudaGetSymbolAddress((void**)&attn, g_attn);
    cudaGetSymbolAddress((void**)&colsum, g_colsum);
    cudaGetSymbolAddress((void**)&biasL, g_biasL);
    cudaGetSymbolAddress((void**)&biasP, g_biasP);

    cudaFuncSetAttribute(mma_gemm<0>, cudaFuncAttributeMaxDynamicSharedMemorySize, MMA_SMEM);
    cudaFuncSetAttribute(mma_gemm<1>, cudaFuncAttributeMaxDynamicSharedMemorySize, MMA_SMEM);
    cudaFuncSetAttribute(mma_apply,   cudaFuncAttributeMaxDynamicSharedMemorySize, MMA_SMEM);
    cudaFuncSetAttribute(gru_kernel,  cudaFuncAttributeMaxDynamicSharedMemorySize, GRU_SMEM_BYTES);

    // 1. operand splits + bias concats
    split_buf(x, xh, xl, (long)MTOT * KX);
    packqT_kernel<<<dim3((KX + 31) / 32, 16), dim3(32, 8)>>>(qh, qd, qTh, qTl);
    split_buf(g1wih, wh + WOFF_W1, wl + WOFF_W1, 768 * 256);
    split_buf(g2wih, wh + WOFF_W2, wl + WOFF_W2, 768 * 256);
    split_buf(fccw,  wh + WOFF_WC, wl + WOFF_WC, (long)NUM_Q * 256);
    split_buf(fctw,  wh + WOFF_WT, wl + WOFF_WT, (long)NUM_Q * 256);
    split_buf(fcew,  wh + WOFF_WE, wl + WOFF_WE, (long)NUM_Q * 512);
    cat2_kernel<<<(2 * 768 + 255) / 256, 256>>>(g1bih, g2bih, biasP, 768);
    cat2_kernel<<<(2 * NUM_Q + 255) / 256, 256>>>(fccb, fctb, biasL, NUM_Q);

    // 2. embeddings -> xe split planes [16000][512]
    launch_mm(1, xh, xl, qTh, qTl, nullptr, xeh, xel, nullptr, 0,
              MTOT, 512, KX, KX, KX, 512, 0, 0, 0, 1);

    // 3. input projections fused over both GRUs: [2][16000][768] fp32
    launch_mm(0, xeh, xel, wh + WOFF_W1, wl + WOFF_W1, xproj, nullptr, nullptr, biasP, 768,
              MTOT, 768, 256, 512, 256, 768, 256, 196608, (long)MTOT * 768, 2);

    // 4. GRU
    gru_kernel<<<dim3(8, 8, 2), 128, GRU_SMEM_BYTES>>>(xproj, g1whh, g2whh, g1bhh, g2bhh, gout);

    // 5. split + transpose-split hidden states
    split_buf(gout, gh, gl, 2L * MTOT * 256);
    transpSplit_kernel<<<dim3(16, 8, 64), dim3(32, 8)>>>(gout, gTh, gTl);

    const bf16 *ghh = gh, *ghl = gl;
    const bf16 *gdh = gh + (long)MTOT * 256, *gdl = gl + (long)MTOT * 256;

    // 6. per-branch logits fused: z=0 -> logit_c, z=1 -> logit_t
    launch_mm(0, ghh, ghl, wh + WOFF_WC, wl + WOFF_WC, out, nullptr, nullptr, biasL, NUM_Q,
              MTOT, NUM_Q, 256, 256, 256, NUM_Q, (long)MTOT * 256, 768000, 48000000L, 2);

    // 7. colsum of out_h
    colsum_kernel<<<BATCH, 256>>>(gout, colsum);

    // 8. attention scores (batched) -> fp32 attn ld 512
    launch_mm(0, ghh, ghl, gdh, gdl, attn, nullptr, nullptr, nullptr, 0,
              SEQ, SEQ, 256, 256, 256, 512, 500L * 256, 500L * 256, 500L * 512, BATCH);

    // 9. softmax -> attn split planes
    softmax_kernel<<<MTOT, 256>>>(attn, ah, al);

    // 10. fused attention apply (both halves of ens in one launch)
    mma_apply<<<dim3(4, 4, BATCH), 256, MMA_SMEM>>>(
        ah, al, gTh + 4194304L, gTl + 4194304L, gTh, gTl, ensh, ensl, colsum);

    // 11. ensemble logits
    launch_mm(0, ensh, ensl, wh + WOFF_WE, wl + WOFF_WE, out + 96000000L, nullptr, nullptr, fceb, 0,
              MTOT, NUM_Q, 512, 512, 512, NUM_Q, 0, 0, 0, 1);
}